// round 2
// baseline (speedup 1.0000x reference)
#include <cuda_runtime.h>
#include <math.h>

// Problem constants
#define BATCH   2
#define HW      64
#define NPIX    4096          // 64*64
#define BN      8192          // BATCH*NPIX tokens
#define DIMQ    64
#define CLD     128
#define KTOK    8
#define FLOW_SZ 1048576       // 2*2*512*512

// Transposed flow-token-encoder weights (prep kernel fills every launch; deterministic)
__device__ float g_w1t[81 * 64];   // g_w1t[c*64+o] = fte_w1[o*81+c]
__device__ float g_w2t[64 * 64];   // g_w2t[c*64+o] = fte_w2[o*64+c]

__device__ __forceinline__ float gelu_exact(float x) {
    return 0.5f * x * (1.0f + erff(x * 0.70710678118654752f));
}

__global__ void prep_kernel(const float* __restrict__ w1, const float* __restrict__ w2) {
    int i = blockIdx.x * blockDim.x + threadIdx.x;
    if (i < 81 * 64) {
        int c = i >> 6, o = i & 63;
        g_w1t[i] = w1[o * 81 + c];
    }
    if (i < 64 * 64) {
        int c = i >> 6, o = i & 63;
        g_w2t[i] = w2[o * 64 + c];
    }
}

__device__ __forceinline__ float samp_map(const float* __restrict__ p, int ix, int iy) {
    if ((unsigned)ix < 64u && (unsigned)iy < 64u) return p[iy * 64 + ix];
    return 0.0f;
}

struct TokSmem {
    float cm[1024];     // cost_memory tile; after K/V proj reused as k_s[0..511], v_s[512..1023]
    float corr[96];     // corr[81]; later reused as attn[64]
    float bufA[64];     // q1 -> attn_out -> ffn hidden
    float bufB[64];     // (qn+enc) -> xn
    float qlin[64];
    float short_s[64];
    float x_s[64];
};

__global__ __launch_bounds__(128) void decoder_kernel(
    const float* __restrict__ cost_maps,
    const float* __restrict__ cost_memory,
    const float* __restrict__ coords1,
    const float* __restrict__ fte_b1,
    const float* __restrict__ fte_b2,
    const float* __restrict__ ln1_g, const float* __restrict__ ln1_b,
    const float* __restrict__ ln2_g, const float* __restrict__ ln2_b,
    const float* __restrict__ wq,  const float* __restrict__ bq,
    const float* __restrict__ wk,  const float* __restrict__ bk,
    const float* __restrict__ wv,  const float* __restrict__ bv,
    const float* __restrict__ wp,  const float* __restrict__ bp,
    const float* __restrict__ fw1, const float* __restrict__ fb1,
    const float* __restrict__ fw2, const float* __restrict__ fb2,
    float* __restrict__ out)
{
    __shared__ TokSmem ts[4];
    const int warp = threadIdx.x >> 5;
    const int lane = threadIdx.x & 31;
    const int n    = blockIdx.x * 4 + warp;     // token id
    TokSmem& S = ts[warp];

    const int b   = n >> 12;
    const int pix = n & 4095;
    const float cx = coords1[b * 8192 + pix];
    const float cy = coords1[b * 8192 + 4096 + pix];
    const int o0 = lane, o1 = lane + 32;

    // ---- load cost_memory tile (coalesced float4) ----
    {
        const float4* cm4 = (const float4*)(cost_memory + (size_t)n * 1024);
        float4* d4 = (float4*)S.cm;
        #pragma unroll
        for (int t = 0; t < 8; ++t) d4[lane + t * 32] = cm4[lane + t * 32];
    }

    // ---- bilinear correlation sampling: 81 samples on this token's own 64x64 map ----
    {
        const float* cmap = cost_maps + (size_t)n * 4096;
        for (int s = lane; s < 81; s += 32) {
            int si = s / 9, sj = s - si * 9;
            float px = cx + (float)(si - 4);   // x offset uses dy-axis index (ref quirk)
            float py = cy + (float)(sj - 4);
            float fx0 = floorf(px), fy0 = floorf(py);
            float wx = px - fx0, wy = py - fy0;
            int ix = (int)fx0, iy = (int)fy0;
            float v00 = samp_map(cmap, ix,     iy);
            float v10 = samp_map(cmap, ix + 1, iy);
            float v01 = samp_map(cmap, ix,     iy + 1);
            float v11 = samp_map(cmap, ix + 1, iy + 1);
            S.corr[s] = v00 * (1.f - wx) * (1.f - wy) + v10 * wx * (1.f - wy)
                      + v01 * (1.f - wx) * wy         + v11 * wx * wy;
        }
    }
    __syncwarp();

    // ---- flow token encoder: q1 = gelu(W1 @ corr + b1) ----
    {
        float a0 = fte_b1[o0], a1 = fte_b1[o1];
        #pragma unroll 3
        for (int c = 0; c < 81; ++c) {
            float cr = S.corr[c];
            a0 = fmaf(cr, g_w1t[c * 64 + o0], a0);
            a1 = fmaf(cr, g_w1t[c * 64 + o1], a1);
        }
        S.bufA[o0] = gelu_exact(a0);
        S.bufA[o1] = gelu_exact(a1);
    }
    __syncwarp();

    // ---- q2 = W2 @ q1 + b2  (= query = short) ----
    float q0 = fte_b2[o0], q1v = fte_b2[o1];
    #pragma unroll 4
    for (int c = 0; c < 64; ++c) {
        float t = S.bufA[c];
        q0  = fmaf(t, g_w2t[c * 64 + o0], q0);
        q1v = fmaf(t, g_w2t[c * 64 + o1], q1v);
    }
    S.short_s[o0] = q0;
    S.short_s[o1] = q1v;

    // ---- layernorm1 (warp reduce over 64 dims = 2 per lane) ----
    {
        float sm = q0 + q1v;
        #pragma unroll
        for (int off = 16; off; off >>= 1) sm += __shfl_xor_sync(0xffffffffu, sm, off);
        float mean = sm * (1.0f / 64.0f);
        float d0 = q0 - mean, d1 = q1v - mean;
        float vs = d0 * d0 + d1 * d1;
        #pragma unroll
        for (int off = 16; off; off >>= 1) vs += __shfl_xor_sync(0xffffffffu, vs, off);
        float inv = rsqrtf(vs * (1.0f / 64.0f) + 1e-5f);

        // linear sine positional encoding: [sin(a) cos(a) sin(b) cos(b)], 16 freqs each
        float enc0, enc1;
        {
            int r = o0 >> 4, f = o0 & 15;
            float base = (r < 2) ? cx : cy;
            float ang = 3.14f * base * (float)f / 200.0f;
            enc0 = ((r & 1) == 0) ? sinf(ang) : cosf(ang);
        }
        {
            int r = o1 >> 4, f = o1 & 15;
            float base = (r < 2) ? cx : cy;
            float ang = 3.14f * base * (float)f / 200.0f;
            enc1 = ((r & 1) == 0) ? sinf(ang) : cosf(ang);
        }
        S.bufB[o0] = d0 * inv * ln1_g[o0] + ln1_b[o0] + enc0;
        S.bufB[o1] = d1 * inv * ln1_g[o1] + ln1_b[o1] + enc1;
    }
    __syncwarp();

    // ---- q projection: qlin = (qn+enc) @ wq + bq ----
    {
        float a0 = bq[o0], a1 = bq[o1];
        #pragma unroll 4
        for (int i = 0; i < 64; ++i) {
            float xv = S.bufB[i];
            a0 = fmaf(xv, wq[i * 64 + o0], a0);
            a1 = fmaf(xv, wq[i * 64 + o1], a1);
        }
        S.qlin[o0] = a0;
        S.qlin[o1] = a1;
    }

    // ---- K/V projections: k[j][d] = cm[j,:] . wk[:,d] + bk[d]  (the FLOP hotspot) ----
    float kacc[16], vacc[16];
    #pragma unroll
    for (int j = 0; j < 16; ++j) { kacc[j] = 0.f; vacc[j] = 0.f; }
    for (int c = 0; c < 128; ++c) {
        float wk0 = wk[c * 64 + o0], wk1 = wk[c * 64 + o1];
        float wv0 = wv[c * 64 + o0], wv1 = wv[c * 64 + o1];
        #pragma unroll
        for (int j = 0; j < 8; ++j) {
            float m = S.cm[j * 128 + c];
            kacc[2 * j]     = fmaf(m, wk0, kacc[2 * j]);
            kacc[2 * j + 1] = fmaf(m, wk1, kacc[2 * j + 1]);
            vacc[2 * j]     = fmaf(m, wv0, vacc[2 * j]);
            vacc[2 * j + 1] = fmaf(m, wv1, vacc[2 * j + 1]);
        }
    }
    __syncwarp();   // everyone done reading S.cm; safe to overwrite with k_s / v_s
    {
        float bk0 = bk[o0], bk1 = bk[o1];
        float bv0 = bv[o0], bv1 = bv[o1];
        float* k_s = S.cm;
        float* v_s = S.cm + 512;
        #pragma unroll
        for (int j = 0; j < 8; ++j) {
            k_s[j * 64 + o0] = kacc[2 * j] + bk0;
            k_s[j * 64 + o1] = kacc[2 * j + 1] + bk1;
            v_s[j * 64 + o0] = vacc[2 * j] + bv0;
            v_s[j * 64 + o1] = vacc[2 * j + 1] + bv1;
        }
    }
    __syncwarp();

    // ---- attention: heads=8, head_dim=8, K=8; lane -> (h, j) pairs ----
    {
        const float* k_s = S.cm;
        int h0 = lane >> 3, jj = lane & 7;
        int h1 = h0 + 4;
        float s0 = 0.f, s1 = 0.f;
        #pragma unroll
        for (int d = 0; d < 8; ++d) {
            s0 = fmaf(S.qlin[h0 * 8 + d], k_s[jj * 64 + h0 * 8 + d], s0);
            s1 = fmaf(S.qlin[h1 * 8 + d], k_s[jj * 64 + h1 * 8 + d], s1);
        }
        s0 *= 0.35355339059327373f;   // 8^-0.5
        s1 *= 0.35355339059327373f;
        // softmax over j within aligned 8-lane groups
        float m0 = s0, m1 = s1;
        #pragma unroll
        for (int off = 4; off; off >>= 1) {
            m0 = fmaxf(m0, __shfl_xor_sync(0xffffffffu, m0, off));
            m1 = fmaxf(m1, __shfl_xor_sync(0xffffffffu, m1, off));
        }
        float e0 = expf(s0 - m0), e1 = expf(s1 - m1);
        float t0 = e0, t1 = e1;
        #pragma unroll
        for (int off = 4; off; off >>= 1) {
            t0 += __shfl_xor_sync(0xffffffffu, t0, off);
            t1 += __shfl_xor_sync(0xffffffffu, t1, off);
        }
        S.corr[h0 * 8 + jj] = e0 / t0;   // attn reuses corr buffer
        S.corr[h1 * 8 + jj] = e1 / t1;
    }
    __syncwarp();

    // ---- attn @ V -> out (into bufA) ----
    {
        const float* v_s = S.cm + 512;
        float a0 = 0.f, a1 = 0.f;
        int h0 = o0 >> 3, h1 = o1 >> 3;
        #pragma unroll
        for (int j = 0; j < 8; ++j) {
            a0 = fmaf(S.corr[h0 * 8 + j], v_s[j * 64 + o0], a0);
            a1 = fmaf(S.corr[h1 * 8 + j], v_s[j * 64 + o1], a1);
        }
        S.bufA[o0] = a0;
        S.bufA[o1] = a1;
    }
    __syncwarp();

    // ---- proj: x = concat(out, short) @ wp + bp + short ----
    float x0 = bp[o0], x1 = bp[o1];
    #pragma unroll 4
    for (int i = 0; i < 64; ++i) {
        float oi = S.bufA[i];
        x0 = fmaf(oi, wp[i * 64 + o0], x0);
        x1 = fmaf(oi, wp[i * 64 + o1], x1);
    }
    #pragma unroll 4
    for (int i = 0; i < 64; ++i) {
        float si = S.short_s[i];
        x0 = fmaf(si, wp[(64 + i) * 64 + o0], x0);
        x1 = fmaf(si, wp[(64 + i) * 64 + o1], x1);
    }
    x0 += S.short_s[o0];
    x1 += S.short_s[o1];

    // ---- layernorm2 ----
    {
        float sm = x0 + x1;
        #pragma unroll
        for (int off = 16; off; off >>= 1) sm += __shfl_xor_sync(0xffffffffu, sm, off);
        float mean = sm * (1.0f / 64.0f);
        float d0 = x0 - mean, d1 = x1 - mean;
        float vs = d0 * d0 + d1 * d1;
        #pragma unroll
        for (int off = 16; off; off >>= 1) vs += __shfl_xor_sync(0xffffffffu, vs, off);
        float inv = rsqrtf(vs * (1.0f / 64.0f) + 1e-5f);
        S.bufB[o0] = d0 * inv * ln2_g[o0] + ln2_b[o0];
        S.bufB[o1] = d1 * inv * ln2_g[o1] + ln2_b[o1];
    }
    __syncwarp();

    // ---- FFN hidden: h = gelu(xn @ fw1 + fb1) ----
    {
        float a0 = fb1[o0], a1 = fb1[o1];
        #pragma unroll 4
        for (int i = 0; i < 64; ++i) {
            float xv = S.bufB[i];
            a0 = fmaf(xv, fw1[i * 64 + o0], a0);
            a1 = fmaf(xv, fw1[i * 64 + o1], a1);
        }
        S.bufA[o0] = gelu_exact(a0);
        S.bufA[o1] = gelu_exact(a1);
    }
    __syncwarp();

    // ---- FFN out + residual ----
    {
        float a0 = fb2[o0], a1 = fb2[o1];
        #pragma unroll 4
        for (int i = 0; i < 64; ++i) {
            float hv = S.bufA[i];
            a0 = fmaf(hv, fw2[i * 64 + o0], a0);
            a1 = fmaf(hv, fw2[i * 64 + o1], a1);
        }
        S.x_s[o0] = x0 + a0;
        S.x_s[o1] = x1 + a1;
    }

    // ---- block-staged transposed writeout: cost_global[b, o, pix] ----
    __syncthreads();
    {
        int n0 = blockIdx.x * 4;
        int bb = n0 >> 12;
        int pix0 = n0 & 4095;
        float* cg = out + FLOW_SZ + (size_t)bb * 64 * 4096;
        for (int idx = threadIdx.x; idx < 256; idx += 128) {
            int o = idx >> 2, t = idx & 3;
            cg[o * 4096 + pix0 + t] = ts[t].x_s[o];
        }
    }
}

// Convex upsampling: each block handles (b, y, 8 consecutive x), 256 threads.
__global__ __launch_bounds__(256) void upsample_kernel(
    const float* __restrict__ coords1,
    const float* __restrict__ up_mask,
    float* __restrict__ out)
{
    __shared__ float slab[576 * 8];    // mask[ch][p] for 8 pixels
    __shared__ float fl[2][3][10];     // 8*flow neighborhood (zero padded)
    __shared__ float outp[2 * 8 * 64];

    int blk = blockIdx.x;
    int b   = blk >> 9;
    int rem = blk & 511;
    int y   = rem >> 3;
    int x0  = (rem & 7) << 3;
    int tid = threadIdx.x;

    const float* mbase = up_mask + (size_t)b * 576 * 4096 + y * 64 + x0;
    for (int idx = tid; idx < 576 * 8; idx += 256) {
        int ch = idx >> 3, p = idx & 7;
        slab[idx] = mbase[(size_t)ch * 4096 + p];
    }
    if (tid < 60) {
        int c = tid / 30, r2 = tid % 30, r = r2 / 10, cc = r2 % 10;
        int yy = y + r - 1, xx = x0 + cc - 1;
        float v = 0.0f;
        if ((unsigned)yy < 64u && (unsigned)xx < 64u) {
            float coord = coords1[b * 8192 + c * 4096 + yy * 64 + xx];
            v = 8.0f * (coord - (float)(c == 0 ? xx : yy));
        }
        fl[c][r][cc] = v;
    }
    __syncthreads();

    for (int q = tid; q < 512; q += 256) {
        int p  = q & 7;
        int ij = q >> 3;
        int i  = ij >> 3, j = ij & 7;
        float w[9];
        float mx = -1e30f;
        #pragma unroll
        for (int kk = 0; kk < 9; ++kk) {
            w[kk] = slab[(kk * 64 + ij) * 8 + p];
            mx = fmaxf(mx, w[kk]);
        }
        float s = 0.f;
        #pragma unroll
        for (int kk = 0; kk < 9; ++kk) { w[kk] = expf(w[kk] - mx); s += w[kk]; }
        float inv = 1.0f / s;
        float u0 = 0.f, u1 = 0.f;
        #pragma unroll
        for (int kk = 0; kk < 9; ++kk) {
            int dy = kk / 3, dx = kk - dy * 3;
            u0 = fmaf(w[kk], fl[0][dy][p + dx], u0);
            u1 = fmaf(w[kk], fl[1][dy][p + dx], u1);
        }
        int col = p * 8 + j;
        outp[(0 * 8 + i) * 64 + col] = u0 * inv;
        outp[(1 * 8 + i) * 64 + col] = u1 * inv;
    }
    __syncthreads();

    float* obase = out + (size_t)b * 2 * 512 * 512 + (size_t)(8 * y) * 512 + 8 * x0;
    for (int idx = tid; idx < 1024; idx += 256) {
        int c = idx >> 9, rest = idx & 511;
        int i = rest >> 6, col = rest & 63;
        obase[(size_t)c * 512 * 512 + i * 512 + col] = outp[(c * 8 + i) * 64 + col];
    }
}

extern "C" void kernel_launch(void* const* d_in, const int* in_sizes, int n_in,
                              void* d_out, int out_size) {
    const float* cost_maps   = (const float*)d_in[0];
    const float* cost_memory = (const float*)d_in[1];
    const float* coords1     = (const float*)d_in[2];
    const float* up_mask     = (const float*)d_in[3];
    const float* fte_w1      = (const float*)d_in[4];
    const float* fte_b1      = (const float*)d_in[5];
    const float* fte_w2      = (const float*)d_in[6];
    const float* fte_b2      = (const float*)d_in[7];
    const float* ln1_g       = (const float*)d_in[8];
    const float* ln1_b       = (const float*)d_in[9];
    const float* ln2_g       = (const float*)d_in[10];
    const float* ln2_b       = (const float*)d_in[11];
    const float* wq          = (const float*)d_in[12];
    const float* bq          = (const float*)d_in[13];
    const float* wk          = (const float*)d_in[14];
    const float* bk          = (const float*)d_in[15];
    const float* wv          = (const float*)d_in[16];
    const float* bv          = (const float*)d_in[17];
    const float* wp          = (const float*)d_in[18];
    const float* bp          = (const float*)d_in[19];
    const float* fw1         = (const float*)d_in[20];
    const float* fb1         = (const float*)d_in[21];
    const float* fw2         = (const float*)d_in[22];
    const float* fb2         = (const float*)d_in[23];
    float* out = (float*)d_out;

    prep_kernel<<<24, 256>>>(fte_w1, fte_w2);
    upsample_kernel<<<1024, 256>>>(coords1, up_mask, out);
    decoder_kernel<<<2048, 128>>>(cost_maps, cost_memory, coords1,
                                  fte_b1, fte_b2,
                                  ln1_g, ln1_b, ln2_g, ln2_b,
                                  wq, bq, wk, bk, wv, bv, wp, bp,
                                  fw1, fb1, fw2, fb2, out);
}